// round 2
// baseline (speedup 1.0000x reference)
#include <cuda_runtime.h>

#define DB 8
#define DN 8192
#define DE 131072
#define DD 128
// BN = 65536 rows total

__device__ float g_h[DB * DN * DD];     // 32 MB: linear output
__device__ float g_agg[DB * DN * DD];   // 32 MB: scatter accumulator
__device__ float g_Wt[DD * DD];         // transposed weights (k-major)
__device__ int   g_idx[DB * 2 * DE];    // normalized int32 edge indices
__device__ int   g_is64;                // dtype flag for edge_index buffer

// ---------------------------------------------------------------------------
// Kernel 0a: detect whether edge_index is int64 or int32 on the wire.
// int64 values in [0,8192) -> every odd 32-bit word is 0 (little-endian).
// ---------------------------------------------------------------------------
__global__ void detect_kernel(const unsigned* __restrict__ eiw) {
    if (threadIdx.x == 0 && blockIdx.x == 0) {
        int ok = 1;
        for (int i = 0; i < 64; i++)
            if (eiw[2 * i + 1] != 0u) { ok = 0; break; }
        g_is64 = ok;
    }
}

// ---------------------------------------------------------------------------
// Kernel 0b: normalize edge indices to int32 scratch (layout preserved).
// ---------------------------------------------------------------------------
__global__ void cvt_idx_kernel(const void* __restrict__ ei) {
    int t = blockIdx.x * 256 + threadIdx.x;           // [0, DB*2*DE)
    int v;
    if (g_is64) v = (int)((const long long*)ei)[t];
    else        v = ((const int*)ei)[t];
    g_idx[t] = v;
}

// ---------------------------------------------------------------------------
// Kernel 0c: transpose W [D_OUT, D_IN] -> Wt [k][c] (k-major for GEMM smem).
// ---------------------------------------------------------------------------
__global__ void prep_kernel(const float* __restrict__ W) {
    int t = blockIdx.x * 256 + threadIdx.x;   // 16384 threads
    int k = t & 127;
    int c = t >> 7;
    g_Wt[k * DD + c] = W[c * DD + k];
}

// ---------------------------------------------------------------------------
// Kernel 1: h = x @ W^T + b, and zero g_agg for the same rows.
// Block = 256 threads, one 32-row tile. Warp computes 4 rows x 128 cols;
// lane owns 4 consecutive output columns (float4). smem = 80 KB dynamic.
// ---------------------------------------------------------------------------
__global__ void gemm_kernel(const float* __restrict__ x, const float* __restrict__ bias) {
    extern __shared__ float sm[];
    float* Ws = sm;               // 128*128
    float* xs = sm + DD * DD;     // 32*128

    float4* Ws4 = (float4*)Ws;
    const float4* Wt4 = (const float4*)g_Wt;
    for (int i = threadIdx.x; i < DD * DD / 4; i += 256) Ws4[i] = Wt4[i];

    int row0 = blockIdx.x * 32;
    const float4* x4 = (const float4*)(x + (size_t)row0 * DD);
    float4* xs4 = (float4*)xs;
    for (int i = threadIdx.x; i < 32 * DD / 4; i += 256) xs4[i] = x4[i];
    __syncthreads();

    int warp = threadIdx.x >> 5;
    int lane = threadIdx.x & 31;
    int r = warp * 4;
    const float* x0 = xs + r * DD;
    const float* x1 = x0 + DD;
    const float* x2 = x1 + DD;
    const float* x3 = x2 + DD;

    float4 a0 = make_float4(0.f, 0.f, 0.f, 0.f);
    float4 a1 = a0, a2 = a0, a3 = a0;

#pragma unroll 8
    for (int k = 0; k < DD; k++) {
        float4 w = Ws4[k * 32 + lane];     // conflict-free LDS.128
        float v0 = x0[k];                  // smem broadcast
        float v1 = x1[k];
        float v2 = x2[k];
        float v3 = x3[k];
        a0.x += v0 * w.x; a0.y += v0 * w.y; a0.z += v0 * w.z; a0.w += v0 * w.w;
        a1.x += v1 * w.x; a1.y += v1 * w.y; a1.z += v1 * w.z; a1.w += v1 * w.w;
        a2.x += v2 * w.x; a2.y += v2 * w.y; a2.z += v2 * w.z; a2.w += v2 * w.w;
        a3.x += v3 * w.x; a3.y += v3 * w.y; a3.z += v3 * w.z; a3.w += v3 * w.w;
    }

    float4 bb = ((const float4*)bias)[lane];
    a0.x += bb.x; a0.y += bb.y; a0.z += bb.z; a0.w += bb.w;
    a1.x += bb.x; a1.y += bb.y; a1.z += bb.z; a1.w += bb.w;
    a2.x += bb.x; a2.y += bb.y; a2.z += bb.z; a2.w += bb.w;
    a3.x += bb.x; a3.y += bb.y; a3.z += bb.z; a3.w += bb.w;

    size_t orow = (size_t)(row0 + r) * DD;
    ((float4*)(g_h + orow))[lane]          = a0;
    ((float4*)(g_h + orow + DD))[lane]     = a1;
    ((float4*)(g_h + orow + 2 * DD))[lane] = a2;
    ((float4*)(g_h + orow + 3 * DD))[lane] = a3;

    float4 z = make_float4(0.f, 0.f, 0.f, 0.f);
    ((float4*)(g_agg + orow))[lane]          = z;
    ((float4*)(g_agg + orow + DD))[lane]     = z;
    ((float4*)(g_agg + orow + 2 * DD))[lane] = z;
    ((float4*)(g_agg + orow + 3 * DD))[lane] = z;
}

// ---------------------------------------------------------------------------
// Kernel 2: scatter-add. One warp per edge: gather h[src] row (128 floats),
// vectorized no-return reduction into agg[dst]. h/agg are L2-resident.
// ---------------------------------------------------------------------------
__global__ void edge_kernel() {
    int w = (blockIdx.x * 256 + threadIdx.x) >> 5;   // global warp id = edge id
    int lane = threadIdx.x & 31;
    int b = w >> 17;              // DE = 2^17
    int e = w & (DE - 1);

    const int* base = g_idx + (size_t)b * 2 * DE;
    int src = base[e];
    int dst = base[DE + e];
    if ((unsigned)src >= DN || (unsigned)dst >= DN) return;  // safety guard

    const float4* hrow = (const float4*)(g_h + (size_t)(b * DN + src) * DD);
    float4 v = hrow[lane];

    float* ap = g_agg + (size_t)(b * DN + dst) * DD + lane * 4;
    asm volatile("red.global.add.v4.f32 [%0], {%1, %2, %3, %4};"
                 :: "l"(ap), "f"(v.x), "f"(v.y), "f"(v.z), "f"(v.w)
                 : "memory");
}

// ---------------------------------------------------------------------------
// Kernel 3: h += agg/sqrt(N); LayerNorm over D=128; ReLU; mask. One warp/row.
// ---------------------------------------------------------------------------
__global__ void final_kernel(const float* __restrict__ mask,
                             const float* __restrict__ gamma,
                             const float* __restrict__ beta,
                             float* __restrict__ out) {
    int w = (blockIdx.x * 256 + threadIdx.x) >> 5;   // row id in [0, 65536)
    int lane = threadIdx.x & 31;

    float4 h = ((const float4*)(g_h + (size_t)w * DD))[lane];
    float4 a = ((const float4*)(g_agg + (size_t)w * DD))[lane];
    const float s = 0.011048543456039806f;  // 1/sqrt(8192)
    float4 v;
    v.x = h.x + a.x * s;
    v.y = h.y + a.y * s;
    v.z = h.z + a.z * s;
    v.w = h.w + a.w * s;

    float sum = v.x + v.y + v.z + v.w;
    float ssq = v.x * v.x + v.y * v.y + v.z * v.z + v.w * v.w;
#pragma unroll
    for (int o = 16; o > 0; o >>= 1) {
        sum += __shfl_xor_sync(0xFFFFFFFFu, sum, o);
        ssq += __shfl_xor_sync(0xFFFFFFFFu, ssq, o);
    }
    float mu = sum * (1.0f / 128.0f);
    float var = ssq * (1.0f / 128.0f) - mu * mu;
    float rstd = rsqrtf(var + 1e-5f);
    float m = mask[w];

    float4 g = ((const float4*)gamma)[lane];
    float4 be = ((const float4*)beta)[lane];
    float4 o4;
    o4.x = fmaxf((v.x - mu) * rstd * g.x + be.x, 0.f) * m;
    o4.y = fmaxf((v.y - mu) * rstd * g.y + be.y, 0.f) * m;
    o4.z = fmaxf((v.z - mu) * rstd * g.z + be.z, 0.f) * m;
    o4.w = fmaxf((v.w - mu) * rstd * g.w + be.w, 0.f) * m;

    ((float4*)out)[(size_t)w * 32 + lane] = o4;
}

// ---------------------------------------------------------------------------
extern "C" void kernel_launch(void* const* d_in, const int* in_sizes, int n_in,
                              void* d_out, int out_size) {
    const float* xf     = (const float*)d_in[0];   // node_features [8,8192,128]
    const void*  ei     = d_in[1];                 // edge_index [8,2,131072] (int32 or int64)
    const float* mask   = (const float*)d_in[2];   // node_mask [8,8192]
    const float* W      = (const float*)d_in[3];   // W [128,128]
    const float* bias   = (const float*)d_in[4];   // b [128]
    const float* gamma  = (const float*)d_in[5];   // gamma [128]
    const float* beta   = (const float*)d_in[6];   // beta [128]
    float* out          = (float*)d_out;

    const int smem_bytes = (DD * DD + 32 * DD) * 4;  // 80 KB
    cudaFuncSetAttribute(gemm_kernel, cudaFuncAttributeMaxDynamicSharedMemorySize, smem_bytes);

    detect_kernel<<<1, 32>>>((const unsigned*)ei);
    cvt_idx_kernel<<<(DB * 2 * DE) / 256, 256>>>(ei);             // 8192 blocks
    prep_kernel<<<64, 256>>>(W);
    gemm_kernel<<<(DB * DN) / 32, 256, smem_bytes>>>(xf, bias);   // 2048 blocks
    edge_kernel<<<(DB * DE) / 8, 256>>>();                        // 131072 blocks, warp/edge
    final_kernel<<<(DB * DN) / 8, 256>>>(mask, gamma, beta, out); // 8192 blocks, warp/row
}

// round 6
// speedup vs baseline: 1.4420x; 1.4420x over previous
#include <cuda_runtime.h>

#define DB 8
#define DN 8192
#define DE 131072
#define DD 128
// 65536 rows total

__device__ float g_h[DB * DN * DD];   // 32 MB: linear output
__device__ float g_Wt[DD * DD];       // transposed weights (k-major)
__device__ int   g_cnt[DB * DN];      // per-dst edge counts
__device__ int   g_off[DB * DN];      // CSR start offsets
__device__ int   g_cur[DB * DN];      // scatter cursors
__device__ int   g_srt[DB * DE];      // src indices sorted by dst
__device__ int   g_is64;              // edge_index dtype flag

// ---------------------------------------------------------------------------
// detect int64 vs int32 edge_index: int64 values < 8192 have all odd 32-bit
// words == 0 (little-endian).
// ---------------------------------------------------------------------------
__global__ void detect_kernel(const unsigned* __restrict__ eiw) {
    if (threadIdx.x == 0) {
        int ok = 1;
        for (int i = 0; i < 64; i++)
            if (eiw[2 * i + 1] != 0u) { ok = 0; break; }
        g_is64 = ok;
    }
}

__global__ void zero_cnt_kernel() {
    g_cnt[blockIdx.x * 256 + threadIdx.x] = 0;
}

__device__ __forceinline__ int load_idx(const void* ei, size_t p) {
    return g_is64 ? (int)((const long long*)ei)[p] : ((const int*)ei)[p];
}

// ---------------------------------------------------------------------------
// histogram of dst degrees
// ---------------------------------------------------------------------------
__global__ void hist_kernel(const void* __restrict__ ei) {
    int t = blockIdx.x * 256 + threadIdx.x;    // [0, DB*DE)
    int b = t >> 17;
    int e = t & (DE - 1);
    int dst = load_idx(ei, ((size_t)b * 2 + 1) * DE + e);
    if ((unsigned)dst < DN) atomicAdd(&g_cnt[b * DN + dst], 1);
}

// ---------------------------------------------------------------------------
// per-batch exclusive prefix sum over 8192 counters (1 block/batch)
// ---------------------------------------------------------------------------
__global__ void scan_kernel() {
    __shared__ int s[1024];
    int b = blockIdx.x;
    int t = threadIdx.x;
    int base = b * DN + t * 8;
    int v[8];
    int sum = 0;
#pragma unroll
    for (int i = 0; i < 8; i++) { v[i] = g_cnt[base + i]; sum += v[i]; }
    s[t] = sum;
    __syncthreads();
    for (int o = 1; o < 1024; o <<= 1) {
        int x = (t >= o) ? s[t - o] : 0;
        __syncthreads();
        s[t] += x;
        __syncthreads();
    }
    int run = s[t] - sum;   // exclusive prefix of this thread's chunk
#pragma unroll
    for (int i = 0; i < 8; i++) {
        g_off[base + i] = run;
        g_cur[base + i] = run;
        run += v[i];
    }
}

// ---------------------------------------------------------------------------
// scatter src ids into dst-sorted order
// ---------------------------------------------------------------------------
__global__ void scatter_kernel(const void* __restrict__ ei) {
    int t = blockIdx.x * 256 + threadIdx.x;    // [0, DB*DE)
    int b = t >> 17;
    int e = t & (DE - 1);
    int src = load_idx(ei, (size_t)b * 2 * DE + e);
    int dst = load_idx(ei, ((size_t)b * 2 + 1) * DE + e);
    if ((unsigned)src >= DN || (unsigned)dst >= DN) return;
    int pos = atomicAdd(&g_cur[b * DN + dst], 1);
    g_srt[(size_t)b * DE + pos] = src;
}

// ---------------------------------------------------------------------------
// transpose W [D_OUT, D_IN] -> Wt [k][c]
// ---------------------------------------------------------------------------
__global__ void prep_kernel(const float* __restrict__ W) {
    int t = blockIdx.x * 256 + threadIdx.x;
    int k = t & 127;
    int c = t >> 7;
    g_Wt[k * DD + c] = W[c * DD + k];
}

// ---------------------------------------------------------------------------
// h = x @ W^T + b. Block = 256 threads, 64 rows; warp = 8 rows x 128 cols,
// lane owns 4 consecutive cols. smem = 96 KB (W k-major + x tile).
// ---------------------------------------------------------------------------
__global__ void gemm_kernel(const float* __restrict__ x, const float* __restrict__ bias) {
    extern __shared__ float sm[];
    float* Ws = sm;               // 128*128
    float* xs = sm + DD * DD;     // 64*128

    float4* Ws4 = (float4*)Ws;
    const float4* Wt4 = (const float4*)g_Wt;
    for (int i = threadIdx.x; i < DD * DD / 4; i += 256) Ws4[i] = Wt4[i];

    int row0 = blockIdx.x * 64;
    const float4* x4 = (const float4*)(x + (size_t)row0 * DD);
    float4* xs4 = (float4*)xs;
    for (int i = threadIdx.x; i < 64 * DD / 4; i += 256) xs4[i] = x4[i];
    __syncthreads();

    int warp = threadIdx.x >> 5;
    int lane = threadIdx.x & 31;
    int r8 = warp * 8;
    const float* xr = xs + r8 * DD;

    float4 acc[8];
#pragma unroll
    for (int r = 0; r < 8; r++) acc[r] = make_float4(0.f, 0.f, 0.f, 0.f);

#pragma unroll 4
    for (int k = 0; k < DD; k++) {
        float4 w = Ws4[k * 32 + lane];          // conflict-free LDS.128
        float xv[8];
#pragma unroll
        for (int r = 0; r < 8; r++) xv[r] = xr[r * DD + k];  // smem broadcast
#pragma unroll
        for (int r = 0; r < 8; r++) {
            acc[r].x += xv[r] * w.x;
            acc[r].y += xv[r] * w.y;
            acc[r].z += xv[r] * w.z;
            acc[r].w += xv[r] * w.w;
        }
    }

    float4 bb = ((const float4*)bias)[lane];
    size_t orow = (size_t)(row0 + r8) * DD;
#pragma unroll
    for (int r = 0; r < 8; r++) {
        float4 o;
        o.x = acc[r].x + bb.x;
        o.y = acc[r].y + bb.y;
        o.z = acc[r].z + bb.z;
        o.w = acc[r].w + bb.w;
        ((float4*)(g_h + orow + (size_t)r * DD))[lane] = o;
    }
}

// ---------------------------------------------------------------------------
// Fused: per-node gather of incident src rows (CSR), + h, LN, ReLU, mask.
// One warp per node; lane owns 4 consecutive cols.
// ---------------------------------------------------------------------------
__global__ void agg_ln_kernel(const float* __restrict__ mask,
                              const float* __restrict__ gamma,
                              const float* __restrict__ beta,
                              float* __restrict__ out) {
    int w = (blockIdx.x * 256 + threadIdx.x) >> 5;   // node id [0, 65536)
    int lane = threadIdx.x & 31;
    int b = w >> 13;

    int start = g_off[w];
    int cnt = g_cnt[w];
    int end = start + cnt;
    const int* srt = g_srt + (size_t)b * DE;
    const float* hb = g_h + (size_t)b * DN * DD;

    float4 acc = make_float4(0.f, 0.f, 0.f, 0.f);
    int j = start;
    for (; j + 4 <= end; j += 4) {
        int s0 = srt[j], s1 = srt[j + 1], s2 = srt[j + 2], s3 = srt[j + 3];
        float4 v0 = ((const float4*)(hb + (size_t)s0 * DD))[lane];
        float4 v1 = ((const float4*)(hb + (size_t)s1 * DD))[lane];
        float4 v2 = ((const float4*)(hb + (size_t)s2 * DD))[lane];
        float4 v3 = ((const float4*)(hb + (size_t)s3 * DD))[lane];
        acc.x += v0.x + v1.x + v2.x + v3.x;
        acc.y += v0.y + v1.y + v2.y + v3.y;
        acc.z += v0.z + v1.z + v2.z + v3.z;
        acc.w += v0.w + v1.w + v2.w + v3.w;
    }
    for (; j < end; j++) {
        int s0 = srt[j];
        float4 v0 = ((const float4*)(hb + (size_t)s0 * DD))[lane];
        acc.x += v0.x; acc.y += v0.y; acc.z += v0.z; acc.w += v0.w;
    }

    float4 h = ((const float4*)(g_h + (size_t)w * DD))[lane];
    const float s = 0.011048543456039806f;  // 1/sqrt(8192)
    float4 v;
    v.x = h.x + acc.x * s;
    v.y = h.y + acc.y * s;
    v.z = h.z + acc.z * s;
    v.w = h.w + acc.w * s;

    float sum = v.x + v.y + v.z + v.w;
    float ssq = v.x * v.x + v.y * v.y + v.z * v.z + v.w * v.w;
#pragma unroll
    for (int o = 16; o > 0; o >>= 1) {
        sum += __shfl_xor_sync(0xFFFFFFFFu, sum, o);
        ssq += __shfl_xor_sync(0xFFFFFFFFu, ssq, o);
    }
    float mu = sum * (1.0f / 128.0f);
    float var = ssq * (1.0f / 128.0f) - mu * mu;
    float rstd = rsqrtf(var + 1e-5f);
    float m = mask[w];

    float4 g = ((const float4*)gamma)[lane];
    float4 be = ((const float4*)beta)[lane];
    float4 o4;
    o4.x = fmaxf((v.x - mu) * rstd * g.x + be.x, 0.f) * m;
    o4.y = fmaxf((v.y - mu) * rstd * g.y + be.y, 0.f) * m;
    o4.z = fmaxf((v.z - mu) * rstd * g.z + be.z, 0.f) * m;
    o4.w = fmaxf((v.w - mu) * rstd * g.w + be.w, 0.f) * m;

    ((float4*)out)[(size_t)w * 32 + lane] = o4;
}

// ---------------------------------------------------------------------------
extern "C" void kernel_launch(void* const* d_in, const int* in_sizes, int n_in,
                              void* d_out, int out_size) {
    const float* xf     = (const float*)d_in[0];   // node_features [8,8192,128]
    const void*  ei     = d_in[1];                 // edge_index [8,2,131072]
    const float* mask   = (const float*)d_in[2];   // node_mask [8,8192]
    const float* W      = (const float*)d_in[3];   // W [128,128]
    const float* bias   = (const float*)d_in[4];   // b [128]
    const float* gamma  = (const float*)d_in[5];   // gamma [128]
    const float* beta   = (const float*)d_in[6];   // beta [128]
    float* out          = (float*)d_out;

    const int smem_bytes = (DD * DD + 64 * DD) * 4;  // 96 KB
    cudaFuncSetAttribute(gemm_kernel, cudaFuncAttributeMaxDynamicSharedMemorySize, smem_bytes);

    detect_kernel<<<1, 32>>>((const unsigned*)ei);
    zero_cnt_kernel<<<(DB * DN) / 256, 256>>>();
    hist_kernel<<<(DB * DE) / 256, 256>>>(ei);
    scan_kernel<<<DB, 1024>>>();
    prep_kernel<<<64, 256>>>(W);
    gemm_kernel<<<(DB * DN) / 64, 256, smem_bytes>>>(xf, bias);   // 1024 blocks
    scatter_kernel<<<(DB * DE) / 256, 256>>>(ei);
    agg_ln_kernel<<<(DB * DN) / 8, 256>>>(mask, gamma, beta, out); // 8192 blocks
}